// round 10
// baseline (speedup 1.0000x reference)
#include <cuda_runtime.h>

#define C_NUM 19
#define DIM   128
#define WPB   4              // warps per block
#define TPB   (WPB * 32)     // 128 threads
#define GRID_N 592           // 4 blocks/SM * 148 SMs -> single wave

__device__ float g_sums[C_NUM * DIM];
__device__ float g_counts[C_NUM];
__device__ float g_loss;
__device__ int   g_tmode;    // 0 = targets are int32[n], 1 = targets are int64[n]

// ---------------------------------------------------------------- probe: detect targets dtype
// View targets as int32. For int64 labels in [0,19), every odd 32-bit word is 0
// (little-endian high word). For int32 labels, P(all odd words == 0) ~ (1/19)^64 ~ 0.
__global__ void k_probe(const int* __restrict__ t32, int n) {
    int lane = threadIdx.x;
    int m = n < 128 ? n : 128;
    int oddnz = 0;
    for (int i = lane; i < m; i += 32)
        if (t32[2 * i + 1] != 0) oddnz = 1;
    unsigned any = __ballot_sync(0xffffffffu, oddnz);
    if (lane == 0) g_tmode = (any == 0u) ? 1 : 0;
}

// ---------------------------------------------------------------- k0: zero scratch
__global__ void k0_zero() {
    int i = threadIdx.x;
    for (int e = i; e < C_NUM * DIM; e += blockDim.x) g_sums[e] = 0.f;
    if (i < C_NUM) g_counts[i] = 0.f;
    if (i == 0) g_loss = 0.f;
}

__device__ __forceinline__ int load_tgt(const int* __restrict__ t32, int r, int sh) {
    int t = t32[r << sh];                 // sh=1: int64 low word; sh=0: int32
    t = t < 0 ? 0 : (t >= C_NUM ? C_NUM - 1 : t);   // crash-proof clamp
    return t;
}

// ---------------------------------------------------------------- k1: per-class sums
// One warp per row (32 lanes x float4 = 128 floats, fully coalesced 512B/row).
// Per-warp PRIVATE shared accumulator [19][128] -> no atomics in the hot loop;
// lane l owns bytes [16l,16l+16) of each class row -> conflict-free LDS.128/STS.128 RMW.
// 4-row unroll for memory-level parallelism over the 577-cyc DRAM latency.
__global__ __launch_bounds__(TPB) void k1_segsum(const float4* __restrict__ x,
                                                 const int* __restrict__ t32,
                                                 int n) {
    __shared__ __align__(16) float acc[WPB][C_NUM * DIM];   // 38,912 B
    __shared__ int cnt[WPB][C_NUM];

    const int tid  = threadIdx.x;
    const int warp = tid >> 5;
    const int lane = tid & 31;
    const int sh   = g_tmode;

    for (int e = tid; e < WPB * C_NUM * DIM; e += TPB) (&acc[0][0])[e] = 0.f;
    for (int e = tid; e < WPB * C_NUM; e += TPB) (&cnt[0][0])[e] = 0;
    __syncthreads();

    const int W  = GRID_N * WPB;          // total warps in grid
    const int gw = blockIdx.x * WPB + warp;
    float* my = acc[warp];

    for (int r = gw; r < n; r += 4 * W) {
        const int r0 = r, r1 = r + W, r2 = r + 2 * W, r3 = r + 3 * W;
        const bool ok1 = r1 < n, ok2 = r2 < n, ok3 = r3 < n;

        // issue all global loads up front (MLP)
        int t0, t1 = 0, t2 = 0, t3 = 0;
        float4 v0, v1, v2, v3;
        t0 = load_tgt(t32, r0, sh); v0 = x[r0 * 32 + lane];
        if (ok1) { t1 = load_tgt(t32, r1, sh); v1 = x[r1 * 32 + lane]; }
        if (ok2) { t2 = load_tgt(t32, r2, sh); v2 = x[r2 * 32 + lane]; }
        if (ok3) { t3 = load_tgt(t32, r3, sh); v3 = x[r3 * 32 + lane]; }

        {
            float4* p = (float4*)(my + t0 * DIM) + lane;
            float4 a = *p;
            a.x += v0.x; a.y += v0.y; a.z += v0.z; a.w += v0.w;
            *p = a;
            if (lane == 0) cnt[warp][t0]++;
        }
        if (ok1) {
            float4* p = (float4*)(my + t1 * DIM) + lane;
            float4 a = *p;
            a.x += v1.x; a.y += v1.y; a.z += v1.z; a.w += v1.w;
            *p = a;
            if (lane == 0) cnt[warp][t1]++;
        }
        if (ok2) {
            float4* p = (float4*)(my + t2 * DIM) + lane;
            float4 a = *p;
            a.x += v2.x; a.y += v2.y; a.z += v2.z; a.w += v2.w;
            *p = a;
            if (lane == 0) cnt[warp][t2]++;
        }
        if (ok3) {
            float4* p = (float4*)(my + t3 * DIM) + lane;
            float4 a = *p;
            a.x += v3.x; a.y += v3.y; a.z += v3.z; a.w += v3.w;
            *p = a;
            if (lane == 0) cnt[warp][t3]++;
        }
    }
    __syncthreads();

    // block-reduce 4 warp accumulators, flush with L2 atomics (2432 addrs, cheap)
    for (int e = tid; e < C_NUM * DIM; e += TPB) {
        float s = acc[0][e] + acc[1][e] + acc[2][e] + acc[3][e];
        atomicAdd(&g_sums[e], s);
    }
    for (int e = tid; e < C_NUM; e += TPB) {
        float s = (float)(cnt[0][e] + cnt[1][e] + cnt[2][e] + cnt[3][e]);
        atomicAdd(&g_counts[e], s);
    }
}

// ---------------------------------------------------------------- k2: distances
// Rows traversed in REVERSE order: k1 streamed forward, so the tail of `inputs`
// is L2-resident when k2 starts -> L2 hits on a chunk of the second pass.
__global__ __launch_bounds__(TPB) void k2_dist(const float4* __restrict__ x,
                                               const int* __restrict__ t32,
                                               int n) {
    __shared__ __align__(16) float ctr[C_NUM * DIM];   // 9,728 B
    __shared__ float wsum[WPB];

    const int tid  = threadIdx.x;
    const int warp = tid >> 5;
    const int lane = tid & 31;
    const int sh   = g_tmode;

    for (int e = tid; e < C_NUM * DIM; e += TPB)
        ctr[e] = g_sums[e] / g_counts[e >> 7];   // e/128 -> class id
    __syncthreads();

    const int W  = GRID_N * WPB;
    const int gw = blockIdx.x * WPB + warp;
    float lsum = 0.f;

    for (int r = gw; r < n; r += 4 * W) {
        const int rv0 = n - 1 - r;
        const int rv1 = rv0 - W, rv2 = rv0 - 2 * W, rv3 = rv0 - 3 * W;
        const bool ok1 = (r + W) < n, ok2 = (r + 2 * W) < n, ok3 = (r + 3 * W) < n;

        int t0, t1 = 0, t2 = 0, t3 = 0;
        float4 v0, v1, v2, v3;
        t0 = load_tgt(t32, rv0, sh); v0 = x[rv0 * 32 + lane];
        if (ok1) { t1 = load_tgt(t32, rv1, sh); v1 = x[rv1 * 32 + lane]; }
        if (ok2) { t2 = load_tgt(t32, rv2, sh); v2 = x[rv2 * 32 + lane]; }
        if (ok3) { t3 = load_tgt(t32, rv3, sh); v3 = x[rv3 * 32 + lane]; }

        float s0, s1 = 0.f, s2 = 0.f, s3 = 0.f;
        {
            float4 c = ((const float4*)(ctr + t0 * DIM))[lane];
            float dx = v0.x - c.x, dy = v0.y - c.y, dz = v0.z - c.z, dw = v0.w - c.w;
            s0 = dx * dx + dy * dy + dz * dz + dw * dw;
        }
        if (ok1) {
            float4 c = ((const float4*)(ctr + t1 * DIM))[lane];
            float dx = v1.x - c.x, dy = v1.y - c.y, dz = v1.z - c.z, dw = v1.w - c.w;
            s1 = dx * dx + dy * dy + dz * dz + dw * dw;
        }
        if (ok2) {
            float4 c = ((const float4*)(ctr + t2 * DIM))[lane];
            float dx = v2.x - c.x, dy = v2.y - c.y, dz = v2.z - c.z, dw = v2.w - c.w;
            s2 = dx * dx + dy * dy + dz * dz + dw * dw;
        }
        if (ok3) {
            float4 c = ((const float4*)(ctr + t3 * DIM))[lane];
            float dx = v3.x - c.x, dy = v3.y - c.y, dz = v3.z - c.z, dw = v3.w - c.w;
            s3 = dx * dx + dy * dy + dz * dz + dw * dw;
        }

        #pragma unroll
        for (int off = 16; off > 0; off >>= 1) {
            s0 += __shfl_xor_sync(0xffffffffu, s0, off);
            s1 += __shfl_xor_sync(0xffffffffu, s1, off);
            s2 += __shfl_xor_sync(0xffffffffu, s2, off);
            s3 += __shfl_xor_sync(0xffffffffu, s3, off);
        }
        if (lane == 0) {
            lsum += sqrtf(s0);
            if (ok1) lsum += sqrtf(s1);
            if (ok2) lsum += sqrtf(s2);
            if (ok3) lsum += sqrtf(s3);
        }
    }

    if (lane == 0) wsum[warp] = lsum;
    __syncthreads();
    if (tid == 0) {
        float s = wsum[0] + wsum[1] + wsum[2] + wsum[3];
        atomicAdd(&g_loss, s);
    }
}

// ---------------------------------------------------------------- k3: finalize
__global__ void k3_final(float* __restrict__ out, int n) {
    if (threadIdx.x == 0) out[0] = g_loss / (float)n;
}

// ---------------------------------------------------------------- launch
extern "C" void kernel_launch(void* const* d_in, const int* in_sizes, int n_in,
                              void* d_out, int out_size) {
    // Resolve input ordering by element count: inputs has 128x the elements of targets.
    const void* a = d_in[0];
    const void* b = d_in[1];
    const float4* x;
    const int*    tgt;
    int n;
    if (in_sizes[0] >= in_sizes[1]) {
        x = (const float4*)a;  tgt = (const int*)b;  n = in_sizes[1];
    } else {
        x = (const float4*)b;  tgt = (const int*)a;  n = in_sizes[0];
    }
    float* out = (float*)d_out;

    k_probe<<<1, 32>>>(tgt, n);
    k0_zero<<<1, 256>>>();
    k1_segsum<<<GRID_N, TPB>>>(x, tgt, n);
    k2_dist<<<GRID_N, TPB>>>(x, tgt, n);
    k3_final<<<1, 32>>>(out, n);
}

// round 11
// speedup vs baseline: 1.0346x; 1.0346x over previous
#include <cuda_runtime.h>

#define C_NUM 19
#define DIM   128
#define WPB   4              // warps per block
#define TPB   (WPB * 32)     // 128 threads
#define GRID_N 592           // 4 blocks/SM * 148 SMs -> single wave

__device__ float g_sums[C_NUM * DIM];
__device__ float g_counts[C_NUM];
__device__ float g_loss;
__device__ int   g_tmode;    // 0 = targets are int32[n], 1 = targets are int64[n]

// ---------------------------------------------------------------- probe: detect targets dtype
// View targets as int32. For int64 labels in [0,19), every odd 32-bit word is 0
// (little-endian high word). For int32 labels, P(all odd words == 0) ~ (1/19)^64 ~ 0.
__global__ void k_probe(const int* __restrict__ t32, int n) {
    int lane = threadIdx.x;
    int m = n < 128 ? n : 128;
    int oddnz = 0;
    for (int i = lane; i < m; i += 32)
        if (t32[2 * i + 1] != 0) oddnz = 1;
    unsigned any = __ballot_sync(0xffffffffu, oddnz);
    if (lane == 0) g_tmode = (any == 0u) ? 1 : 0;
}

// ---------------------------------------------------------------- k0: zero scratch
__global__ void k0_zero() {
    int i = threadIdx.x;
    for (int e = i; e < C_NUM * DIM; e += blockDim.x) g_sums[e] = 0.f;
    if (i < C_NUM) g_counts[i] = 0.f;
    if (i == 0) g_loss = 0.f;
}

__device__ __forceinline__ int load_tgt(const int* __restrict__ t32, int r, int sh) {
    int t = t32[r << sh];                 // sh=1: int64 low word; sh=0: int32
    t = t < 0 ? 0 : (t >= C_NUM ? C_NUM - 1 : t);   // crash-proof clamp
    return t;
}

// ---------------------------------------------------------------- k1: per-class sums
// One warp per row (32 lanes x float4 = 128 floats, fully coalesced 512B/row).
// Per-warp PRIVATE shared accumulator [19][128] -> no atomics in the hot loop;
// lane l owns bytes [16l,16l+16) of each class row -> conflict-free LDS.128/STS.128 RMW.
// 4-row unroll for memory-level parallelism over the 577-cyc DRAM latency.
__global__ __launch_bounds__(TPB) void k1_segsum(const float4* __restrict__ x,
                                                 const int* __restrict__ t32,
                                                 int n) {
    __shared__ __align__(16) float acc[WPB][C_NUM * DIM];   // 38,912 B
    __shared__ int cnt[WPB][C_NUM];

    const int tid  = threadIdx.x;
    const int warp = tid >> 5;
    const int lane = tid & 31;
    const int sh   = g_tmode;

    for (int e = tid; e < WPB * C_NUM * DIM; e += TPB) (&acc[0][0])[e] = 0.f;
    for (int e = tid; e < WPB * C_NUM; e += TPB) (&cnt[0][0])[e] = 0;
    __syncthreads();

    const int W  = GRID_N * WPB;          // total warps in grid
    const int gw = blockIdx.x * WPB + warp;
    float* my = acc[warp];

    for (int r = gw; r < n; r += 4 * W) {
        const int r0 = r, r1 = r + W, r2 = r + 2 * W, r3 = r + 3 * W;
        const bool ok1 = r1 < n, ok2 = r2 < n, ok3 = r3 < n;

        // issue all global loads up front (MLP)
        int t0, t1 = 0, t2 = 0, t3 = 0;
        float4 v0, v1, v2, v3;
        t0 = load_tgt(t32, r0, sh); v0 = x[r0 * 32 + lane];
        if (ok1) { t1 = load_tgt(t32, r1, sh); v1 = x[r1 * 32 + lane]; }
        if (ok2) { t2 = load_tgt(t32, r2, sh); v2 = x[r2 * 32 + lane]; }
        if (ok3) { t3 = load_tgt(t32, r3, sh); v3 = x[r3 * 32 + lane]; }

        {
            float4* p = (float4*)(my + t0 * DIM) + lane;
            float4 a = *p;
            a.x += v0.x; a.y += v0.y; a.z += v0.z; a.w += v0.w;
            *p = a;
            if (lane == 0) cnt[warp][t0]++;
        }
        if (ok1) {
            float4* p = (float4*)(my + t1 * DIM) + lane;
            float4 a = *p;
            a.x += v1.x; a.y += v1.y; a.z += v1.z; a.w += v1.w;
            *p = a;
            if (lane == 0) cnt[warp][t1]++;
        }
        if (ok2) {
            float4* p = (float4*)(my + t2 * DIM) + lane;
            float4 a = *p;
            a.x += v2.x; a.y += v2.y; a.z += v2.z; a.w += v2.w;
            *p = a;
            if (lane == 0) cnt[warp][t2]++;
        }
        if (ok3) {
            float4* p = (float4*)(my + t3 * DIM) + lane;
            float4 a = *p;
            a.x += v3.x; a.y += v3.y; a.z += v3.z; a.w += v3.w;
            *p = a;
            if (lane == 0) cnt[warp][t3]++;
        }
    }
    __syncthreads();

    // block-reduce 4 warp accumulators, flush with L2 atomics (2432 addrs, cheap)
    for (int e = tid; e < C_NUM * DIM; e += TPB) {
        float s = acc[0][e] + acc[1][e] + acc[2][e] + acc[3][e];
        atomicAdd(&g_sums[e], s);
    }
    for (int e = tid; e < C_NUM; e += TPB) {
        float s = (float)(cnt[0][e] + cnt[1][e] + cnt[2][e] + cnt[3][e]);
        atomicAdd(&g_counts[e], s);
    }
}

// ---------------------------------------------------------------- k2: distances
// Rows traversed in REVERSE order: k1 streamed forward, so the tail of `inputs`
// is L2-resident when k2 starts -> L2 hits on a chunk of the second pass.
__global__ __launch_bounds__(TPB) void k2_dist(const float4* __restrict__ x,
                                               const int* __restrict__ t32,
                                               int n) {
    __shared__ __align__(16) float ctr[C_NUM * DIM];   // 9,728 B
    __shared__ float wsum[WPB];

    const int tid  = threadIdx.x;
    const int warp = tid >> 5;
    const int lane = tid & 31;
    const int sh   = g_tmode;

    for (int e = tid; e < C_NUM * DIM; e += TPB)
        ctr[e] = g_sums[e] / g_counts[e >> 7];   // e/128 -> class id
    __syncthreads();

    const int W  = GRID_N * WPB;
    const int gw = blockIdx.x * WPB + warp;
    float lsum = 0.f;

    for (int r = gw; r < n; r += 4 * W) {
        const int rv0 = n - 1 - r;
        const int rv1 = rv0 - W, rv2 = rv0 - 2 * W, rv3 = rv0 - 3 * W;
        const bool ok1 = (r + W) < n, ok2 = (r + 2 * W) < n, ok3 = (r + 3 * W) < n;

        int t0, t1 = 0, t2 = 0, t3 = 0;
        float4 v0, v1, v2, v3;
        t0 = load_tgt(t32, rv0, sh); v0 = x[rv0 * 32 + lane];
        if (ok1) { t1 = load_tgt(t32, rv1, sh); v1 = x[rv1 * 32 + lane]; }
        if (ok2) { t2 = load_tgt(t32, rv2, sh); v2 = x[rv2 * 32 + lane]; }
        if (ok3) { t3 = load_tgt(t32, rv3, sh); v3 = x[rv3 * 32 + lane]; }

        float s0, s1 = 0.f, s2 = 0.f, s3 = 0.f;
        {
            float4 c = ((const float4*)(ctr + t0 * DIM))[lane];
            float dx = v0.x - c.x, dy = v0.y - c.y, dz = v0.z - c.z, dw = v0.w - c.w;
            s0 = dx * dx + dy * dy + dz * dz + dw * dw;
        }
        if (ok1) {
            float4 c = ((const float4*)(ctr + t1 * DIM))[lane];
            float dx = v1.x - c.x, dy = v1.y - c.y, dz = v1.z - c.z, dw = v1.w - c.w;
            s1 = dx * dx + dy * dy + dz * dz + dw * dw;
        }
        if (ok2) {
            float4 c = ((const float4*)(ctr + t2 * DIM))[lane];
            float dx = v2.x - c.x, dy = v2.y - c.y, dz = v2.z - c.z, dw = v2.w - c.w;
            s2 = dx * dx + dy * dy + dz * dz + dw * dw;
        }
        if (ok3) {
            float4 c = ((const float4*)(ctr + t3 * DIM))[lane];
            float dx = v3.x - c.x, dy = v3.y - c.y, dz = v3.z - c.z, dw = v3.w - c.w;
            s3 = dx * dx + dy * dy + dz * dz + dw * dw;
        }

        #pragma unroll
        for (int off = 16; off > 0; off >>= 1) {
            s0 += __shfl_xor_sync(0xffffffffu, s0, off);
            s1 += __shfl_xor_sync(0xffffffffu, s1, off);
            s2 += __shfl_xor_sync(0xffffffffu, s2, off);
            s3 += __shfl_xor_sync(0xffffffffu, s3, off);
        }
        if (lane == 0) {
            lsum += sqrtf(s0);
            if (ok1) lsum += sqrtf(s1);
            if (ok2) lsum += sqrtf(s2);
            if (ok3) lsum += sqrtf(s3);
        }
    }

    if (lane == 0) wsum[warp] = lsum;
    __syncthreads();
    if (tid == 0) {
        float s = wsum[0] + wsum[1] + wsum[2] + wsum[3];
        atomicAdd(&g_loss, s);
    }
}

// ---------------------------------------------------------------- k3: finalize
__global__ void k3_final(float* __restrict__ out, int n) {
    if (threadIdx.x == 0) out[0] = g_loss / (float)n;
}

// ---------------------------------------------------------------- launch
extern "C" void kernel_launch(void* const* d_in, const int* in_sizes, int n_in,
                              void* d_out, int out_size) {
    // Resolve input ordering by element count: inputs has 128x the elements of targets.
    const void* a = d_in[0];
    const void* b = d_in[1];
    const float4* x;
    const int*    tgt;
    int n;
    if (in_sizes[0] >= in_sizes[1]) {
        x = (const float4*)a;  tgt = (const int*)b;  n = in_sizes[1];
    } else {
        x = (const float4*)b;  tgt = (const int*)a;  n = in_sizes[0];
    }
    float* out = (float*)d_out;

    k_probe<<<1, 32>>>(tgt, n);
    k0_zero<<<1, 256>>>();
    k1_segsum<<<GRID_N, TPB>>>(x, tgt, n);
    k2_dist<<<GRID_N, TPB>>>(x, tgt, n);
    k3_final<<<1, 32>>>(out, n);
}

// round 12
// speedup vs baseline: 1.1976x; 1.1576x over previous
#include <cuda_runtime.h>

#define C_NUM 19
#define DIM   128

// ---- k1 config: smem-limited to 5 blocks/SM (38.9KB acc each) ----
#define K1_WPB   4
#define K1_TPB   (K1_WPB * 32)
#define K1_GRID  740            // 5 blocks/SM * 148 SMs -> single wave
#define K1_UNROLL 8

// ---- k2 config: occupancy-driven ----
#define K2_WPB   8
#define K2_TPB   (K2_WPB * 32)  // 256 threads
#define K2_GRID  888            // 6 blocks/SM * 148 SMs; 48 warps/SM (RF-capped)

__device__ float g_sums[C_NUM * DIM];
__device__ float g_counts[C_NUM];
__device__ float g_loss;
__device__ int   g_tmode;    // 0 = targets int32[n], 1 = targets int64[n]

// ---------------------------------------------------------------- k0: zero + dtype probe
// Probe: view targets as int32. int64 labels in [0,19) -> every odd word is 0
// (little-endian high word). For genuine int32 labels P(all zero) ~ (1/19)^64 ~ 0.
__global__ void k0_zero_probe(const int* __restrict__ t32, int n) {
    int tid = threadIdx.x;
    for (int e = tid; e < C_NUM * DIM; e += blockDim.x) g_sums[e] = 0.f;
    if (tid < C_NUM) g_counts[tid] = 0.f;
    if (tid == 0) g_loss = 0.f;

    if (tid < 32) {
        int m = n < 128 ? n : 128;
        int oddnz = 0;
        for (int i = tid; i < m; i += 32)
            if (t32[2 * i + 1] != 0) oddnz = 1;
        unsigned any = __ballot_sync(0xffffffffu, oddnz);
        if (tid == 0) g_tmode = (any == 0u) ? 1 : 0;
    }
}

__device__ __forceinline__ int load_tgt(const int* __restrict__ t32, int r, int sh) {
    int t = t32[r << sh];                          // sh=1: int64 low word; sh=0: int32
    return t < 0 ? 0 : (t >= C_NUM ? C_NUM - 1 : t);
}

// ---------------------------------------------------------------- k1: per-class sums
// One warp per row (32 lanes x float4 = 128 floats, coalesced 512B/row).
// Per-warp PRIVATE shared accumulator [19][128] -> no hot-loop atomics; lane l
// owns bytes [16l,16l+16) of each class row -> conflict-free LDS.128/STS.128 RMW.
// 8-row unroll for MLP over the 577-cyc DRAM latency.
__global__ __launch_bounds__(K1_TPB) void k1_segsum(const float4* __restrict__ x,
                                                    const int* __restrict__ t32,
                                                    int n) {
    __shared__ __align__(16) float acc[K1_WPB][C_NUM * DIM];   // 38,912 B
    __shared__ int cnt[K1_WPB][C_NUM];

    const int tid  = threadIdx.x;
    const int warp = tid >> 5;
    const int lane = tid & 31;
    const int sh   = g_tmode;

    for (int e = tid; e < K1_WPB * C_NUM * DIM; e += K1_TPB) (&acc[0][0])[e] = 0.f;
    for (int e = tid; e < K1_WPB * C_NUM; e += K1_TPB) (&cnt[0][0])[e] = 0;
    __syncthreads();

    const int W  = K1_GRID * K1_WPB;
    const int gw = blockIdx.x * K1_WPB + warp;
    float* my = acc[warp];

    for (int r = gw; r < n; r += K1_UNROLL * W) {
        int    t[K1_UNROLL];
        float4 v[K1_UNROLL];
        bool   ok[K1_UNROLL];

        // issue all global loads up front (MLP)
        #pragma unroll
        for (int u = 0; u < K1_UNROLL; u++) {
            int ri = r + u * W;
            ok[u] = ri < n;
            if (ok[u]) { t[u] = load_tgt(t32, ri, sh); v[u] = x[ri * 32 + lane]; }
        }

        #pragma unroll
        for (int u = 0; u < K1_UNROLL; u++) {
            if (ok[u]) {
                float4* p = (float4*)(my + t[u] * DIM) + lane;
                float4 a = *p;
                a.x += v[u].x; a.y += v[u].y; a.z += v[u].z; a.w += v[u].w;
                *p = a;
                if (lane == 0) cnt[warp][t[u]]++;
            }
        }
    }
    __syncthreads();

    // block-reduce 4 warp accumulators, flush with L2 atomics (2432 addrs, cheap)
    for (int e = tid; e < C_NUM * DIM; e += K1_TPB) {
        float s = acc[0][e] + acc[1][e] + acc[2][e] + acc[3][e];
        atomicAdd(&g_sums[e], s);
    }
    for (int e = tid; e < C_NUM; e += K1_TPB) {
        float s = (float)(cnt[0][e] + cnt[1][e] + cnt[2][e] + cnt[3][e]);
        atomicAdd(&g_counts[e], s);
    }
}

// ---------------------------------------------------------------- k2: distances
// Rows traversed in REVERSE order (k1 streamed forward -> tail may be L2-resident).
__global__ __launch_bounds__(K2_TPB) void k2_dist(const float4* __restrict__ x,
                                                  const int* __restrict__ t32,
                                                  int n) {
    __shared__ __align__(16) float ctr[C_NUM * DIM];   // 9,728 B
    __shared__ float wsum[K2_WPB];

    const int tid  = threadIdx.x;
    const int warp = tid >> 5;
    const int lane = tid & 31;
    const int sh   = g_tmode;

    for (int e = tid; e < C_NUM * DIM; e += K2_TPB)
        ctr[e] = g_sums[e] / g_counts[e >> 7];   // e/128 -> class id
    __syncthreads();

    const int W  = K2_GRID * K2_WPB;
    const int gw = blockIdx.x * K2_WPB + warp;
    float lsum = 0.f;

    for (int r = gw; r < n; r += 4 * W) {
        const int rv0 = n - 1 - r;
        const int rv1 = rv0 - W, rv2 = rv0 - 2 * W, rv3 = rv0 - 3 * W;
        const bool ok1 = (r + W) < n, ok2 = (r + 2 * W) < n, ok3 = (r + 3 * W) < n;

        int t0, t1 = 0, t2 = 0, t3 = 0;
        float4 v0, v1, v2, v3;
        t0 = load_tgt(t32, rv0, sh); v0 = x[rv0 * 32 + lane];
        if (ok1) { t1 = load_tgt(t32, rv1, sh); v1 = x[rv1 * 32 + lane]; }
        if (ok2) { t2 = load_tgt(t32, rv2, sh); v2 = x[rv2 * 32 + lane]; }
        if (ok3) { t3 = load_tgt(t32, rv3, sh); v3 = x[rv3 * 32 + lane]; }

        float s0, s1 = 0.f, s2 = 0.f, s3 = 0.f;
        {
            float4 c = ((const float4*)(ctr + t0 * DIM))[lane];
            float dx = v0.x - c.x, dy = v0.y - c.y, dz = v0.z - c.z, dw = v0.w - c.w;
            s0 = dx * dx + dy * dy + dz * dz + dw * dw;
        }
        if (ok1) {
            float4 c = ((const float4*)(ctr + t1 * DIM))[lane];
            float dx = v1.x - c.x, dy = v1.y - c.y, dz = v1.z - c.z, dw = v1.w - c.w;
            s1 = dx * dx + dy * dy + dz * dz + dw * dw;
        }
        if (ok2) {
            float4 c = ((const float4*)(ctr + t2 * DIM))[lane];
            float dx = v2.x - c.x, dy = v2.y - c.y, dz = v2.z - c.z, dw = v2.w - c.w;
            s2 = dx * dx + dy * dy + dz * dz + dw * dw;
        }
        if (ok3) {
            float4 c = ((const float4*)(ctr + t3 * DIM))[lane];
            float dx = v3.x - c.x, dy = v3.y - c.y, dz = v3.z - c.z, dw = v3.w - c.w;
            s3 = dx * dx + dy * dy + dz * dz + dw * dw;
        }

        #pragma unroll
        for (int off = 16; off > 0; off >>= 1) {
            s0 += __shfl_xor_sync(0xffffffffu, s0, off);
            s1 += __shfl_xor_sync(0xffffffffu, s1, off);
            s2 += __shfl_xor_sync(0xffffffffu, s2, off);
            s3 += __shfl_xor_sync(0xffffffffu, s3, off);
        }
        if (lane == 0) {
            lsum += sqrtf(s0);
            if (ok1) lsum += sqrtf(s1);
            if (ok2) lsum += sqrtf(s2);
            if (ok3) lsum += sqrtf(s3);
        }
    }

    if (lane == 0) wsum[warp] = lsum;
    __syncthreads();
    if (tid == 0) {
        float s = 0.f;
        #pragma unroll
        for (int w = 0; w < K2_WPB; w++) s += wsum[w];
        atomicAdd(&g_loss, s);
    }
}

// ---------------------------------------------------------------- k3: finalize
__global__ void k3_final(float* __restrict__ out, int n) {
    if (threadIdx.x == 0) out[0] = g_loss / (float)n;
}

// ---------------------------------------------------------------- launch
extern "C" void kernel_launch(void* const* d_in, const int* in_sizes, int n_in,
                              void* d_out, int out_size) {
    // Resolve input ordering by element count: inputs has 128x the elements of targets.
    const void* a = d_in[0];
    const void* b = d_in[1];
    const float4* x;
    const int*    tgt;
    int n;
    if (in_sizes[0] >= in_sizes[1]) {
        x = (const float4*)a;  tgt = (const int*)b;  n = in_sizes[1];
    } else {
        x = (const float4*)b;  tgt = (const int*)a;  n = in_sizes[0];
    }
    float* out = (float*)d_out;

    k0_zero_probe<<<1, 256>>>(tgt, n);
    k1_segsum<<<K1_GRID, K1_TPB>>>(x, tgt, n);
    k2_dist<<<K2_GRID, K2_TPB>>>(x, tgt, n);
    k3_final<<<1, 32>>>(out, n);
}